// round 1
// baseline (speedup 1.0000x reference)
#include <cuda_runtime.h>
#include <cuda_bf16.h>
#include <cooperative_groups.h>

namespace cg = cooperative_groups;

// Problem constants (fixed by the dataset)
#define BB    8        // batch
#define TT    4096     // time steps
#define FF    512      // input features
#define CC    128      // reduced input
#define UU    256      // LSTM units
#define OO    64       // output features
#define G4    1024     // 4*U

// -------- scratch (device globals; no allocation allowed) --------
__device__ float g_xr[(size_t)BB * TT * CC];   // 16 MB
__device__ float g_z [(size_t)BB * TT * G4];   // 128 MB
__device__ float g_hs[(size_t)BB * TT * UU];   // 32 MB

// ---------------- packed f32x2 helpers ----------------
__device__ __forceinline__ unsigned long long packf2(float lo, float hi) {
    unsigned long long r;
    asm("mov.b64 %0, {%1, %2};" : "=l"(r) : "f"(lo), "f"(hi));
    return r;
}
__device__ __forceinline__ void fma2(unsigned long long& d,
                                     unsigned long long a,
                                     unsigned long long b) {
    asm("fma.rn.f32x2 %0, %1, %2, %0;" : "+l"(d) : "l"(a), "l"(b));
}
__device__ __forceinline__ float reduce2(unsigned long long d) {
    float lo, hi;
    asm("mov.b64 {%0, %1}, %2;" : "=f"(lo), "=f"(hi) : "l"(d));
    return lo + hi;
}

// ---------------- fast activations (MUFU-based, ~1e-7 rel err) ----------------
__device__ __forceinline__ float fsig(float x) {
    return 1.0f / (1.0f + __expf(-x));
}
__device__ __forceinline__ float ftanh(float x) {
    x = fminf(fmaxf(x, -15.0f), 15.0f);
    float e = __expf(2.0f * x);
    return (e - 1.0f) / (e + 1.0f);
}

// =====================================================================
// Generic fp32 tiled GEMM: C[M,N] = A[M,K] * B[K,N] + bias[N]
// BM x BN block tile, BK k-tile, TM x TN register microtile.
// Assumes M%BM==0, N%BN==0, K%BK==0, K%4==0, BK%4==0, TN%4==0.
// =====================================================================
template <int BM, int BN, int BK, int TM, int TN, int NT>
__global__ void __launch_bounds__(NT)
gemm_bias_kernel(const float* __restrict__ A, const float* __restrict__ Bm,
                 const float* __restrict__ bias, float* __restrict__ C,
                 int M, int N, int K) {
    __shared__ __align__(16) float As[BK][BM];
    __shared__ __align__(16) float Bs[BK][BN];

    const int tx = threadIdx.x % (BN / TN);
    const int ty = threadIdx.x / (BN / TN);
    const int rowBase = blockIdx.y * BM;
    const int colBase = blockIdx.x * BN;

    float acc[TM][TN];
#pragma unroll
    for (int i = 0; i < TM; i++)
#pragma unroll
        for (int j = 0; j < TN; j++) acc[i][j] = 0.0f;

    for (int k0 = 0; k0 < K; k0 += BK) {
        // load A tile (transposed into As[k][m])
#pragma unroll 2
        for (int idx = threadIdx.x; idx < BM * BK / 4; idx += NT) {
            int r  = idx / (BK / 4);
            int kc = (idx % (BK / 4)) * 4;
            float4 v = *(const float4*)&A[(size_t)(rowBase + r) * K + k0 + kc];
            As[kc + 0][r] = v.x;
            As[kc + 1][r] = v.y;
            As[kc + 2][r] = v.z;
            As[kc + 3][r] = v.w;
        }
        // load B tile
#pragma unroll 2
        for (int idx = threadIdx.x; idx < BK * BN / 4; idx += NT) {
            int kr = idx / (BN / 4);
            int cc = (idx % (BN / 4)) * 4;
            *(float4*)&Bs[kr][cc] =
                *(const float4*)&Bm[(size_t)(k0 + kr) * N + colBase + cc];
        }
        __syncthreads();

#pragma unroll
        for (int kk = 0; kk < BK; kk++) {
            float ra[TM], rb[TN];
#pragma unroll
            for (int i = 0; i < TM; i++) ra[i] = As[kk][ty * TM + i];
#pragma unroll
            for (int j = 0; j < TN; j++) rb[j] = Bs[kk][tx * TN + j];
#pragma unroll
            for (int i = 0; i < TM; i++)
#pragma unroll
                for (int j = 0; j < TN; j++)
                    acc[i][j] = fmaf(ra[i], rb[j], acc[i][j]);
        }
        __syncthreads();
    }

    // epilogue with bias, vectorized
#pragma unroll
    for (int i = 0; i < TM; i++) {
        int row = rowBase + ty * TM + i;
#pragma unroll
        for (int j = 0; j < TN; j += 4) {
            int col = colBase + tx * TN + j;
            float4 b4 = *(const float4*)&bias[col];
            float4 o;
            o.x = acc[i][j + 0] + b4.x;
            o.y = acc[i][j + 1] + b4.y;
            o.z = acc[i][j + 2] + b4.z;
            o.w = acc[i][j + 3] + b4.w;
            *(float4*)&C[(size_t)row * N + col] = o;
        }
    }
}

// =====================================================================
// LSTM recurrence. Grid = 64 CTAs = 8 clusters (one per batch element)
// of 8 CTAs. Each CTA owns 32 units (128 gate columns), keeps its
// rec_kernel slice [256,128] in registers as f32x2 pairs (256 thr x 64
// pairs), cell state in warp-0 lanes. h exchanged via DSMEM, double-
// buffered, one cluster.sync per step.
// =====================================================================
#define LSTM_NTH 256
#define CLSZ     8

__global__ void __cluster_dims__(CLSZ, 1, 1) __launch_bounds__(LSTM_NTH, 1)
lstm_kernel(const float* __restrict__ rec_kernel) {
    cg::cluster_group cluster = cg::this_cluster();
    const int rank  = cluster.block_rank();        // 0..7 within cluster
    const int batch = blockIdx.x / CLSZ;           // 0..7
    const int tid   = threadIdx.x;

    const int c  = tid & 127;   // gate-column within this CTA's 128-col slice
    const int s  = tid >> 7;    // K-half: 0 -> k[0,128), 1 -> k[128,256)
    const int g  = c >> 5;      // gate: 0=i,1=f,2=g,3=o
    const int lu = c & 31;      // local unit
    const int u  = rank * 32 + lu;
    const int colIdx = (g << 8) + u;               // column in [0,1024)

    __shared__ __align__(16) float hbuf[2][UU];
    __shared__ float part[2][128];
    __shared__ float act[128];

    // ---- load weight slice into registers as packed pairs ----
    unsigned long long w2[64];
#pragma unroll
    for (int m = 0; m < 64; m++) {
        float a = rec_kernel[(size_t)(s * 128 + 2 * m)     * G4 + colIdx];
        float b = rec_kernel[(size_t)(s * 128 + 2 * m + 1) * G4 + colIdx];
        w2[m] = packf2(a, b);
    }

    // ---- precompute peer h-buffer pointers (used by warp 0) ----
    float* dst0[CLSZ];
    float* dst1[CLSZ];
#pragma unroll
    for (int r = 0; r < CLSZ; r++) {
        dst0[r] = (float*)cluster.map_shared_rank((void*)hbuf[0], r);
        dst1[r] = (float*)cluster.map_shared_rank((void*)hbuf[1], r);
    }

    // ---- init state ----
    for (int i = tid; i < 2 * UU; i += LSTM_NTH) ((float*)hbuf)[i] = 0.0f;
    float cst = 0.0f;   // cell state (meaningful in warp-0 lanes)
    cluster.sync();     // everyone's buffers zeroed before any remote write

    const float* zbase = g_z + (size_t)batch * TT * G4 + colIdx;
    float zin = (s == 0) ? zbase[0] : 0.0f;   // prefetch t=0
    float* hsbase = g_hs + (size_t)batch * TT * UU;

    int p = 0;
#pragma unroll 1
    for (int t = 0; t < TT; t++) {
        // ---- z_partial = h[p] (my K-half) dot my weight column ----
        unsigned long long acc2 = 0ULL;
        const float4* h4 = (const float4*)hbuf[p];
#pragma unroll
        for (int m = 0; m < 32; m++) {
            float4 hv = h4[s * 32 + m];
            fma2(acc2, w2[2 * m],     packf2(hv.x, hv.y));
            fma2(acc2, w2[2 * m + 1], packf2(hv.z, hv.w));
        }
        part[s][c] = reduce2(acc2);
        __syncthreads();

        if (tid < 128) {
            float z = part[0][c] + part[1][c] + zin;
            if (t + 1 < TT) zin = zbase[(size_t)(t + 1) * G4];  // prefetch
            act[c] = (g == 2) ? ftanh(z) : fsig(z);
        }
        __syncthreads();

        if (tid < 32) {
            float ai = act[tid];
            float af = act[32 + tid];
            float ag = act[64 + tid];
            float ao = act[96 + tid];
            cst = af * cst + ai * ag;
            float hval = ao * ftanh(cst);
            int uw = rank * 32 + tid;
            hsbase[(size_t)t * UU + uw] = hval;
            float** dst = (p == 0) ? dst1 : dst0;   // write next buffer
#pragma unroll
            for (int r = 0; r < CLSZ; r++) dst[r][uw] = hval;
        }
        cluster.sync();   // release DSMEM h-writes, all CTAs step together
        p ^= 1;
    }
}

// =====================================================================
// Launch
// =====================================================================
extern "C" void kernel_launch(void* const* d_in, const int* in_sizes, int n_in,
                              void* d_out, int out_size) {
    const float* x          = (const float*)d_in[0];  // [8,4096,512]
    const float* w_in       = (const float*)d_in[1];  // [512,128]
    const float* b_in       = (const float*)d_in[2];  // [128]
    const float* kern       = (const float*)d_in[3];  // [128,1024]
    const float* rec_kernel = (const float*)d_in[4];  // [256,1024]
    const float* bias       = (const float*)d_in[5];  // [1024]
    const float* w_out      = (const float*)d_in[6];  // [256,64]
    const float* b_out      = (const float*)d_in[7];  // [64]
    float* out = (float*)d_out;                       // [8,4096,64]

    float* xr = nullptr;
    float* zz = nullptr;
    float* hs = nullptr;
    cudaGetSymbolAddress((void**)&xr, g_xr);
    cudaGetSymbolAddress((void**)&zz, g_z);
    cudaGetSymbolAddress((void**)&hs, g_hs);

    const int M = BB * TT;  // 32768

    // 1) xr = x @ w_in + b_in       [32768,512] x [512,128]
    gemm_bias_kernel<128, 128, 8, 8, 8, 256>
        <<<dim3(CC / 128, M / 128), 256>>>(x, w_in, b_in, xr, M, CC, FF);

    // 2) z = xr @ kernel + bias     [32768,128] x [128,1024]
    gemm_bias_kernel<128, 128, 8, 8, 8, 256>
        <<<dim3(G4 / 128, M / 128), 256>>>(xr, kern, bias, zz, M, G4, CC);

    // 3) LSTM recurrence: 8 clusters x 8 CTAs
    lstm_kernel<<<BB * CLSZ, LSTM_NTH>>>(rec_kernel);

    // 4) out = hs @ w_out + b_out   [32768,256] x [256,64]
    gemm_bias_kernel<128, 64, 8, 8, 4, 256>
        <<<dim3(OO / 64, M / 128), 256>>>(hs, w_out, b_out, out, M, OO, UU);
}